// round 12
// baseline (speedup 1.0000x reference)
#include <cuda_runtime.h>

#define X 256
#define Y 256
#define Z 192
#define YX (X*Y)
#define NB 2
#define TX 64           // output tile width
#define TY 32           // output tile height
#define CW 34           // float2 cells per row = (TX+4)/2
#define CH 36           // rows = TY+4 (divisible by 3)
#define TCY 12          // thread rows: each owns 3 adjacent rows
#define NTH (CW*TCY)    // 408 threads
#define ZCHUNKS 12
#define ZCK (Z/ZCHUNKS) /* 16 */

__device__ __forceinline__ float min3(float a, float b, float c) { return fminf(a, fminf(b, c)); }
__device__ __forceinline__ float max3(float a, float b, float c) { return fmaxf(a, fmaxf(b, c)); }
__device__ __forceinline__ float2 fmin3_2(float2 a, float2 b, float2 c) {
    return make_float2(min3(a.x,b.x,c.x), min3(a.y,b.y,c.y));
}
__device__ __forceinline__ float2 fmax3_2(float2 a, float2 b, float2 c) {
    return make_float2(max3(a.x,b.x,c.x), max3(a.y,b.y,c.y));
}

// out = relu(img - dilate3x3x3(erode3x3x3(img))), stride 1, pad 1.
// erode = min-pool (pad +inf), dilate = max-pool (pad -inf via domain mask).
// Thread owns THREE adjacent y-rows of one float2 cell: the middle row's
// y-window is in-register, and the y-exchanges need only the two edge rows
// (store r0,r2; read prev.r2/next.r0). 4.33 uniform LDS.64 smem ops and 0.67
// barrier participations per output voxel (vs 5.0 / 1.0 in the 84.7us champ).
__global__ __launch_bounds__(NTH, 3)
void soft_skel_kernel(const float* __restrict__ img, float* __restrict__ out) {
    __shared__ float2 sA[CH * CW];
    __shared__ float2 sB[CH * CW];

    const int tid = threadIdx.x;
    const int tc  = tid % CW;            // cell index
    const int tr  = tid / CW;            // owns rows 3tr, 3tr+1, 3tr+2
    const int bx0 = blockIdx.x * TX;
    const int by0 = blockIdx.y * TY;
    const int bz  = blockIdx.z;
    const int b   = bz / ZCHUNKS;
    const int z0  = (bz % ZCHUNKS) * ZCK;
    const int z1  = z0 + ZCK;

    const int gx  = bx0 + 2*tc - 2;      // x of cell (even)
    const int r0  = 3*tr;                // local rows r0, r0+1, r0+2
    const int gy0 = by0 + r0 - 2;

    const bool inx  = (gx >= 0) && (gx < X);      // cell uniformly in/out in x
    const bool iny0 = (gy0     >= 0) && (gy0     < Y);
    const bool iny1 = (gy0 + 1 >= 0) && (gy0 + 1 < Y);
    const bool iny2 = (gy0 + 2 >= 0) && (gy0 + 2 < Y);

    // output: rows 2..33, cells 1..32
    const bool outC  = (tc >= 1) && (tc <= CW - 2);
    const bool oR0   = outC && (r0     >= 2) && (r0     <= 33);
    const bool oR1   = outC && (r0 + 1 >= 2) && (r0 + 1 <= 33);
    const bool oR2   = outC && (r0 + 2 >= 2) && (r0 + 2 <= 33);

    // smem offsets (float2 units); clamps leave garbage only in shell rows
    const int xl = (tc == 0)       ? 0      : tc - 1;
    const int xr = (tc == CW - 1)  ? CW - 1 : tc + 1;
    const int yu = (tr == 0)       ? 0      : r0 - 1;   // prev thread's r2
    const int yd = (tr == TCY - 1) ? CH - 1 : r0 + 3;   // next thread's r0
    const int o0 = (r0    ) * CW + tc;
    const int o1 = (r0 + 1) * CW + tc;
    const int o2 = (r0 + 2) * CW + tc;
    const int oU = yu * CW + tc;
    const int oD = yd * CW + tc;
    const int oL0 = (r0    ) * CW + xl, oR0x = (r0    ) * CW + xr;
    const int oL1 = (r0 + 1) * CW + xl, oR1x = (r0 + 1) * CW + xr;
    const int oL2 = (r0 + 2) * CW + xl, oR2x = (r0 + 2) * CW + xr;

    const float  PINF = __int_as_float(0x7f800000);
    const float  NINF = __int_as_float(0xff800000);
    const float2 PI2  = make_float2(PINF, PINF);
    const float2 NI2  = make_float2(NINF, NINF);

    const long base = (long)b * Z * YX + (long)gy0 * X + gx;
    const float* pIn = img + base;       // + z*YX
    float*       pO  = out + base + (long)z0 * YX;

    // rings: p = img planes (zi-2, zi-1, zi) x 3 rows; q = erode (zi-3, zi-2)
    float2 p0[3], p1[3], p2[3];
    float2 q0[3], q1[3];
    #pragma unroll
    for (int r = 0; r < 3; ++r) { p0[r] = PI2; p1[r] = PI2; q0[r] = NI2; q1[r] = NI2; }

    #define LOADP(dst, zz) do {                                                \
        const int _z = (zz);                                                   \
        const bool _zk = (unsigned)_z < (unsigned)Z;                           \
        const long _o = (long)_z * YX;                                         \
        dst[0] = (_zk && iny0 && inx) ? *(const float2*)(pIn + _o)         : PI2; \
        dst[1] = (_zk && iny1 && inx) ? *(const float2*)(pIn + _o + X)     : PI2; \
        dst[2] = (_zk && iny2 && inx) ? *(const float2*)(pIn + _o + 2*X)   : PI2; \
    } while (0)

    LOADP(p2, z0 - 2);

    for (int zi = z0 - 2; zi <= z1 + 1; ++zi) {
        // ---- prefetch plane zi+1 (issued 4 barrier-phases before use)
        float2 pn[3];
        LOADP(pn, zi + 1);

        // ---- erode-z (registers) at plane zc = zi-1
        float2 zm0 = fmin3_2(p0[0], p1[0], p2[0]);
        float2 zm1 = fmin3_2(p0[1], p1[1], p2[1]);
        float2 zm2 = fmin3_2(p0[2], p1[2], p2[2]);

        // ---- erode-y via smem (buffer A): edge rows only
        sA[o0] = zm0;
        sA[o2] = zm2;
        __syncthreads();
        float2 U = sA[oU];
        float2 D = sA[oD];
        float2 yb0 = fmin3_2(U,   zm0, zm1);
        float2 yb1 = fmin3_2(zm0, zm1, zm2);
        float2 yb2 = fmin3_2(zm1, zm2, D);

        sB[o0] = yb0;
        sB[o1] = yb1;
        sB[o2] = yb2;
        __syncthreads();

        // ---- erode-x + domain mask (-inf outside => dilate padding)
        const int  zc  = zi - 1;
        const bool zin = (unsigned)zc < (unsigned)Z;
        float2 en0, en1, en2;
        {
            float2 L0 = sB[oL0], Rx0 = sB[oR0x];
            float2 L1 = sB[oL1], Rx1 = sB[oR1x];
            float2 L2 = sB[oL2], Rx2 = sB[oR2x];
            const bool m0 = zin && iny0 && inx;
            const bool m1 = zin && iny1 && inx;
            const bool m2 = zin && iny2 && inx;
            en0.x = m0 ? min3(L0.y,  yb0.x, yb0.y) : NINF;
            en0.y = m0 ? min3(yb0.x, yb0.y, Rx0.x) : NINF;
            en1.x = m1 ? min3(L1.y,  yb1.x, yb1.y) : NINF;
            en1.y = m1 ? min3(yb1.x, yb1.y, Rx1.x) : NINF;
            en2.x = m2 ? min3(L2.y,  yb2.x, yb2.y) : NINF;
            en2.y = m2 ? min3(yb2.x, yb2.y, Rx2.x) : NINF;
        }

        // ---- dilate-z (registers) at plane zo = zi-2
        float2 dd0 = fmax3_2(q0[0], q1[0], en0);
        float2 dd1 = fmax3_2(q0[1], q1[1], en1);
        float2 dd2 = fmax3_2(q0[2], q1[2], en2);
        q0[0] = q1[0]; q1[0] = en0;
        q0[1] = q1[1]; q1[1] = en1;
        q0[2] = q1[2]; q1[2] = en2;

        // ---- dilate-y via smem (buffer A; its readers finished pre-sync2)
        sA[o0] = dd0;
        sA[o2] = dd2;
        __syncthreads();
        float2 U2 = sA[oU];
        float2 D2 = sA[oD];
        float2 m0 = fmax3_2(U2,  dd0, dd1);
        float2 m1 = fmax3_2(dd0, dd1, dd2);
        float2 m2 = fmax3_2(dd1, dd2, D2);

        sB[o0] = m0;
        sB[o1] = m1;
        sB[o2] = m2;
        __syncthreads();

        // ---- dilate-x + output at plane zo = zi-2
        if (zi >= z0 + 2) {
            float2 L0 = sB[oL0], Rx0 = sB[oR0x];
            float2 L1 = sB[oL1], Rx1 = sB[oR1x];
            float2 L2 = sB[oL2], Rx2 = sB[oR2x];
            if (oR0) {
                float2 r;
                r.x = fmaxf(p0[0].x - max3(L0.y,  m0.x, m0.y), 0.0f);
                r.y = fmaxf(p0[0].y - max3(m0.x, m0.y, Rx0.x), 0.0f);
                *(float2*)pO = r;                    // p0 = img at plane zo
            }
            if (oR1) {
                float2 r;
                r.x = fmaxf(p0[1].x - max3(L1.y,  m1.x, m1.y), 0.0f);
                r.y = fmaxf(p0[1].y - max3(m1.x, m1.y, Rx1.x), 0.0f);
                *(float2*)(pO + X) = r;
            }
            if (oR2) {
                float2 r;
                r.x = fmaxf(p0[2].x - max3(L2.y,  m2.x, m2.y), 0.0f);
                r.y = fmaxf(p0[2].y - max3(m2.x, m2.y, Rx2.x), 0.0f);
                *(float2*)(pO + 2*X) = r;
            }
            pO += YX;
        }

        // ---- shift img rings
        #pragma unroll
        for (int r = 0; r < 3; ++r) { p0[r] = p1[r]; p1[r] = p2[r]; p2[r] = pn[r]; }
    }
    #undef LOADP
}

extern "C" void kernel_launch(void* const* d_in, const int* in_sizes, int n_in,
                              void* d_out, int out_size) {
    (void)in_sizes; (void)n_in; (void)out_size;
    const float* img = (const float*)d_in[0];
    float* out = (float*)d_out;
    dim3 grid(X / TX, Y / TY, NB * ZCHUNKS);
    soft_skel_kernel<<<grid, NTH>>>(img, out);
}

// round 13
// speedup vs baseline: 3.0082x; 3.0082x over previous
#include <cuda_runtime.h>

#define X 256
#define Y 256
#define Z 192
#define YX (X*Y)
#define NB 2
#define TX 64          // output tile width (elements)
#define TY 32          // output tile height
#define CW 34          // float2 columns = (TX+4)/2
#define CH 36          // rows = TY+4 (halo 2 each side)
#define TR 18          // thread-rows: each thread owns 2 adjacent rows
#define NTH (CW*TR)    // 612 threads
#define ZCHUNKS 8
#define ZCK (Z/ZCHUNKS) /* 24 */

__device__ __forceinline__ float2 fmin2(float2 a, float2 b) {
    return make_float2(fminf(a.x, b.x), fminf(a.y, b.y));
}
__device__ __forceinline__ float2 fmax2(float2 a, float2 b) {
    return make_float2(fmaxf(a.x, b.x), fmaxf(a.y, b.y));
}
__device__ __forceinline__ float2 fmin3_2(float2 a, float2 b, float2 c) {
    return fmin2(a, fmin2(b, c));
}
__device__ __forceinline__ float2 fmax3_2(float2 a, float2 b, float2 c) {
    return fmax2(a, fmax2(b, c));
}

// out = relu(img - dilate3x3x3(erode3x3x3(img))), stride 1, pad 1.
// erode = min-pool (pad +inf), dilate = max-pool (pad -inf via domain mask).
// Champion structure (84.7us): thread owns TWO adjacent y-rows of a float2
// column; 4 uniform LDS.64 ping-pong rounds per plane; register z-rings.
// This round: the z-march is peeled into FILL (4 planes, no output) and
// STEADY (unconditional output) phases so the hot loop carries no output
// predicate or conditional pointer bump.
__global__ __launch_bounds__(NTH, 2)
void soft_skel_kernel(const float* __restrict__ img, float* __restrict__ out) {
    __shared__ float2 sA[CH * CW];
    __shared__ float2 sB[CH * CW];

    const int tid = threadIdx.x;
    const int cx  = tid % CW;            // float2 column index
    const int ry  = tid / CW;            // thread-row (owns rows 2ry, 2ry+1)
    const int iy0 = 2 * ry;
    const int iy1 = iy0 + 1;
    const int bx0 = blockIdx.x * TX;
    const int by0 = blockIdx.y * TY;
    const int bz  = blockIdx.z;
    const int b   = bz / ZCHUNKS;
    const int z0  = (bz % ZCHUNKS) * ZCK;

    const int gx  = bx0 + cx * 2 - 2;    // first element of the pair (even)
    const int gy0 = by0 + iy0 - 2;
    const int gy1 = gy0 + 1;

    const bool inX  = (gx >= 0) && (gx < X);     // pair uniformly in/out in x
    const bool in0  = inX && (gy0 >= 0) && (gy0 < Y);
    const bool in1  = inX && (gy1 >= 0) && (gy1 < Y);
    const bool outP = (ry >= 1) && (ry <= TR - 2) && (cx >= 1) && (cx <= CW - 2);

    // loop-invariant smem offsets (clamps leave garbage only in the outer
    // shell rows 0/35 and cols 0/33, never consumed by interior outputs)
    const int xl = (cx == 0)      ? 0      : cx - 1;
    const int xr = (cx == CW - 1) ? CW - 1 : cx + 1;
    const int yu = (ry == 0)      ? 0      : iy0 - 1;
    const int yd = (ry == TR - 1) ? CH - 1 : iy1 + 1;
    const int off0  = iy0 * CW + cx;
    const int off1  = iy1 * CW + cx;
    const int offU  = yu  * CW + cx;
    const int offD  = yd  * CW + cx;
    const int off0L = iy0 * CW + xl, off0R = iy0 * CW + xr;
    const int off1L = iy1 * CW + xl, off1R = iy1 * CW + xr;

    const float  PINF = __int_as_float(0x7f800000);
    const float  NINF = __int_as_float(0xff800000);
    const float2 PI2  = make_float2(PINF, PINF);
    const float2 NI2  = make_float2(NINF, NINF);

    const long base = (long)b * Z * YX + (long)gy0 * X + gx;
    const float* pIn = img + base;
    float*       pO  = out + base + (long)z0 * YX;

    // rings: a*/b* = img rows iy0/iy1 (planes zi-2, zi-1, zi); e* = erode
    float2 a0 = PI2, a1 = PI2, a2;
    float2 b0 = PI2, b1 = PI2, b2;
    float2 ea0 = NI2, ea1 = NI2;
    float2 eb0 = NI2, eb1 = NI2;

    // masked dual-row plane load
    #define LOADP(dA_, dB_, zz) do {                                       \
        const int _z = (zz);                                               \
        const bool _zk = (unsigned)_z < (unsigned)Z;                       \
        const long _o = (long)_z * YX;                                     \
        dA_ = (_zk && in0) ? *(const float2*)(pIn + _o)     : PI2;         \
        dB_ = (_zk && in1) ? *(const float2*)(pIn + _o + X) : PI2;         \
    } while (0)

    // one full plane of pipeline work at plane index zi (erode zc=zi-1,
    // dilate zo=zi-2 left in sB + registers). EMIT: write output plane zo.
    #define PLANE_BODY(zi_, EMIT) do {                                     \
        float2 an, bn;                                                     \
        LOADP(an, bn, (zi_) + 1);                                          \
        float2 zmA = fmin3_2(a0, a1, a2);                                  \
        float2 zmB = fmin3_2(b0, b1, b2);                                  \
        sA[off0] = zmA;                                                    \
        sA[off1] = zmB;                                                    \
        __syncthreads();                                                   \
        float2 up = sA[offU];                                              \
        float2 dn = sA[offD];                                              \
        float2 ybA = fmin3_2(up,  zmA, zmB);                               \
        float2 ybB = fmin3_2(zmA, zmB, dn);                                \
        sB[off0] = ybA;                                                    \
        sB[off1] = ybB;                                                    \
        __syncthreads();                                                   \
        float2 LA = sB[off0L], RA = sB[off0R];                             \
        float2 LB = sB[off1L], RB = sB[off1R];                             \
        const bool zin = (unsigned)((zi_) - 1) < (unsigned)Z;              \
        const bool v0v = in0 && zin;                                       \
        const bool v1v = in1 && zin;                                       \
        float2 enA, enB;                                                   \
        enA.x = v0v ? fminf(LA.y, fminf(ybA.x, ybA.y)) : NINF;             \
        enA.y = v0v ? fminf(ybA.x, fminf(ybA.y, RA.x)) : NINF;             \
        enB.x = v1v ? fminf(LB.y, fminf(ybB.x, ybB.y)) : NINF;             \
        enB.y = v1v ? fminf(ybB.x, fminf(ybB.y, RB.x)) : NINF;             \
        float2 dA = fmax3_2(ea0, ea1, enA);                                \
        float2 dB = fmax3_2(eb0, eb1, enB);                                \
        ea0 = ea1; ea1 = enA;                                              \
        eb0 = eb1; eb1 = enB;                                              \
        sA[off0] = dA;                                                     \
        sA[off1] = dB;                                                     \
        __syncthreads();                                                   \
        float2 upd = sA[offU];                                             \
        float2 dnd = sA[offD];                                             \
        float2 mA = fmax3_2(upd, dA, dB);                                  \
        float2 mB = fmax3_2(dA,  dB, dnd);                                 \
        sB[off0] = mA;                                                     \
        sB[off1] = mB;                                                     \
        __syncthreads();                                                   \
        if (EMIT) {                                                        \
            if (outP) {                                                    \
                float2 LmA = sB[off0L], RmA = sB[off0R];                   \
                float2 LmB = sB[off1L], RmB = sB[off1R];                   \
                float2 r0_, r1_;                                           \
                r0_.x = fmaxf(a0.x - fmaxf(LmA.y, fmaxf(mA.x, mA.y)), 0.0f); \
                r0_.y = fmaxf(a0.y - fmaxf(mA.x, fmaxf(mA.y, RmA.x)), 0.0f); \
                r1_.x = fmaxf(b0.x - fmaxf(LmB.y, fmaxf(mB.x, mB.y)), 0.0f); \
                r1_.y = fmaxf(b0.y - fmaxf(mB.x, fmaxf(mB.y, RmB.x)), 0.0f); \
                *(float2*)pO       = r0_;   /* a0/b0 = img at plane zo */  \
                *(float2*)(pO + X) = r1_;                                  \
            }                                                              \
            pO += YX;                                                      \
        }                                                                  \
        a0 = a1; a1 = a2; a2 = an;                                         \
        b0 = b1; b1 = b2; b2 = bn;                                         \
    } while (0)

    // preload plane z0-2
    LOADP(a2, b2, z0 - 2);

    // ---- FILL: planes z0-2 .. z0+1 (no output)
    PLANE_BODY(z0 - 2, false);
    PLANE_BODY(z0 - 1, false);
    PLANE_BODY(z0,     false);
    PLANE_BODY(z0 + 1, false);

    // ---- STEADY: planes z0+2 .. z0+ZCK+1, unconditional output
    #pragma unroll 1
    for (int zi = z0 + 2; zi <= z0 + ZCK + 1; ++zi) {
        PLANE_BODY(zi, true);
    }

    #undef PLANE_BODY
    #undef LOADP
}

extern "C" void kernel_launch(void* const* d_in, const int* in_sizes, int n_in,
                              void* d_out, int out_size) {
    (void)in_sizes; (void)n_in; (void)out_size;
    const float* img = (const float*)d_in[0];
    float* out = (float*)d_out;
    dim3 grid(X / TX, Y / TY, NB * ZCHUNKS);
    soft_skel_kernel<<<grid, NTH>>>(img, out);
}

// round 14
// speedup vs baseline: 3.2396x; 1.0770x over previous
#include <cuda_runtime.h>

#define X 256
#define Y 256
#define Z 192
#define YX (X*Y)
#define NB 2
#define TX 64          // output tile width (elements)
#define TY 32          // output tile height
#define CW 34          // float2 columns = (TX+4)/2
#define CH 36          // rows = TY+4 (halo 2 each side)
#define TR 18          // thread-rows: each thread owns 2 adjacent rows
#define NTH (CW*TR)    // 612 threads
#define ZCHUNKS 4
#define ZCK (Z/ZCHUNKS) /* 48 */

__device__ __forceinline__ float2 fmin2(float2 a, float2 b) {
    return make_float2(fminf(a.x, b.x), fminf(a.y, b.y));
}
__device__ __forceinline__ float2 fmax2(float2 a, float2 b) {
    return make_float2(fmaxf(a.x, b.x), fmaxf(a.y, b.y));
}
__device__ __forceinline__ float2 fmin3_2(float2 a, float2 b, float2 c) {
    return fmin2(a, fmin2(b, c));
}
__device__ __forceinline__ float2 fmax3_2(float2 a, float2 b, float2 c) {
    return fmax2(a, fmax2(b, c));
}

// out = relu(img - dilate3x3x3(erode3x3x3(img))), stride 1, pad 1.
// erode = min-pool (pad +inf), dilate = max-pool (pad -inf via domain mask).
// Champion structure: thread owns TWO adjacent y-rows of a float2 column;
// 4 uniform LDS.64 ping-pong rounds per plane; register z-rings; peeled
// fill/steady phases. This round: (1) the two dead fill bodies (whose erode
// planes z0-3, z0-2 no output consumes) are replaced by direct ring preloads;
// (2) ZCHUNKS=4 -> 256 blocks = one clean 2-per-SM wave, critical path
// 2 x (ZCK+2) = 100 plane-bodies per SM instead of 4 x 28 = 112.
__global__ __launch_bounds__(NTH, 2)
void soft_skel_kernel(const float* __restrict__ img, float* __restrict__ out) {
    __shared__ float2 sA[CH * CW];
    __shared__ float2 sB[CH * CW];

    const int tid = threadIdx.x;
    const int cx  = tid % CW;            // float2 column index
    const int ry  = tid / CW;            // thread-row (owns rows 2ry, 2ry+1)
    const int iy0 = 2 * ry;
    const int iy1 = iy0 + 1;
    const int bx0 = blockIdx.x * TX;
    const int by0 = blockIdx.y * TY;
    const int bz  = blockIdx.z;
    const int b   = bz / ZCHUNKS;
    const int z0  = (bz % ZCHUNKS) * ZCK;

    const int gx  = bx0 + cx * 2 - 2;    // first element of the pair (even)
    const int gy0 = by0 + iy0 - 2;
    const int gy1 = gy0 + 1;

    const bool inX  = (gx >= 0) && (gx < X);     // pair uniformly in/out in x
    const bool in0  = inX && (gy0 >= 0) && (gy0 < Y);
    const bool in1  = inX && (gy1 >= 0) && (gy1 < Y);
    const bool outP = (ry >= 1) && (ry <= TR - 2) && (cx >= 1) && (cx <= CW - 2);

    // loop-invariant smem offsets (clamps leave garbage only in the outer
    // shell rows 0/35 and cols 0/33, never consumed by interior outputs)
    const int xl = (cx == 0)      ? 0      : cx - 1;
    const int xr = (cx == CW - 1) ? CW - 1 : cx + 1;
    const int yu = (ry == 0)      ? 0      : iy0 - 1;
    const int yd = (ry == TR - 1) ? CH - 1 : iy1 + 1;
    const int off0  = iy0 * CW + cx;
    const int off1  = iy1 * CW + cx;
    const int offU  = yu  * CW + cx;
    const int offD  = yd  * CW + cx;
    const int off0L = iy0 * CW + xl, off0R = iy0 * CW + xr;
    const int off1L = iy1 * CW + xl, off1R = iy1 * CW + xr;

    const float  PINF = __int_as_float(0x7f800000);
    const float  NINF = __int_as_float(0xff800000);
    const float2 PI2  = make_float2(PINF, PINF);
    const float2 NI2  = make_float2(NINF, NINF);

    const long base = (long)b * Z * YX + (long)gy0 * X + gx;
    const float* pIn = img + base;
    float*       pO  = out + base + (long)z0 * YX;

    // rings: a*/b* = img rows iy0/iy1 (planes zi-2, zi-1, zi); e* = erode
    float2 a0, a1, a2, b0, b1, b2;
    float2 ea0 = NI2, ea1 = NI2;
    float2 eb0 = NI2, eb1 = NI2;

    // masked dual-row plane load
    #define LOADP(dA_, dB_, zz) do {                                       \
        const int _z = (zz);                                               \
        const bool _zk = (unsigned)_z < (unsigned)Z;                       \
        const long _o = (long)_z * YX;                                     \
        dA_ = (_zk && in0) ? *(const float2*)(pIn + _o)     : PI2;         \
        dB_ = (_zk && in1) ? *(const float2*)(pIn + _o + X) : PI2;         \
    } while (0)

    // one full plane of pipeline work at plane index zi (erode zc=zi-1,
    // dilate zo=zi-2 left in sB + registers). EMIT: write output plane zo.
    #define PLANE_BODY(zi_, EMIT) do {                                     \
        float2 an, bn;                                                     \
        LOADP(an, bn, (zi_) + 1);                                          \
        float2 zmA = fmin3_2(a0, a1, a2);                                  \
        float2 zmB = fmin3_2(b0, b1, b2);                                  \
        sA[off0] = zmA;                                                    \
        sA[off1] = zmB;                                                    \
        __syncthreads();                                                   \
        float2 up = sA[offU];                                              \
        float2 dn = sA[offD];                                              \
        float2 ybA = fmin3_2(up,  zmA, zmB);                               \
        float2 ybB = fmin3_2(zmA, zmB, dn);                                \
        sB[off0] = ybA;                                                    \
        sB[off1] = ybB;                                                    \
        __syncthreads();                                                   \
        float2 LA = sB[off0L], RA = sB[off0R];                             \
        float2 LB = sB[off1L], RB = sB[off1R];                             \
        const bool zin = (unsigned)((zi_) - 1) < (unsigned)Z;              \
        const bool v0v = in0 && zin;                                       \
        const bool v1v = in1 && zin;                                       \
        float2 enA, enB;                                                   \
        enA.x = v0v ? fminf(LA.y, fminf(ybA.x, ybA.y)) : NINF;             \
        enA.y = v0v ? fminf(ybA.x, fminf(ybA.y, RA.x)) : NINF;             \
        enB.x = v1v ? fminf(LB.y, fminf(ybB.x, ybB.y)) : NINF;             \
        enB.y = v1v ? fminf(ybB.x, fminf(ybB.y, RB.x)) : NINF;             \
        float2 dA = fmax3_2(ea0, ea1, enA);                                \
        float2 dB = fmax3_2(eb0, eb1, enB);                                \
        ea0 = ea1; ea1 = enA;                                              \
        eb0 = eb1; eb1 = enB;                                              \
        sA[off0] = dA;                                                     \
        sA[off1] = dB;                                                     \
        __syncthreads();                                                   \
        float2 upd = sA[offU];                                             \
        float2 dnd = sA[offD];                                             \
        float2 mA = fmax3_2(upd, dA, dB);                                  \
        float2 mB = fmax3_2(dA,  dB, dnd);                                 \
        sB[off0] = mA;                                                     \
        sB[off1] = mB;                                                     \
        __syncthreads();                                                   \
        if (EMIT) {                                                        \
            if (outP) {                                                    \
                float2 LmA = sB[off0L], RmA = sB[off0R];                   \
                float2 LmB = sB[off1L], RmB = sB[off1R];                   \
                float2 r0_, r1_;                                           \
                r0_.x = fmaxf(a0.x - fmaxf(LmA.y, fmaxf(mA.x, mA.y)), 0.0f); \
                r0_.y = fmaxf(a0.y - fmaxf(mA.x, fmaxf(mA.y, RmA.x)), 0.0f); \
                r1_.x = fmaxf(b0.x - fmaxf(LmB.y, fmaxf(mB.x, mB.y)), 0.0f); \
                r1_.y = fmaxf(b0.y - fmaxf(mB.x, fmaxf(mB.y, RmB.x)), 0.0f); \
                *(float2*)pO       = r0_;   /* a0/b0 = img at plane zo */  \
                *(float2*)(pO + X) = r1_;                                  \
            }                                                              \
            pO += YX;                                                      \
        }                                                                  \
        a0 = a1; a1 = a2; a2 = an;                                         \
        b0 = b1; b1 = b2; b2 = bn;                                         \
    } while (0)

    // ---- direct ring preload: img planes z0-2, z0-1, z0 (no smem, no sync)
    LOADP(a0, b0, z0 - 2);
    LOADP(a1, b1, z0 - 1);
    LOADP(a2, b2, z0);

    // ---- FILL: bodies at zi = z0, z0+1 compute erode z0-1, z0 (no output)
    PLANE_BODY(z0,     false);
    PLANE_BODY(z0 + 1, false);

    // ---- STEADY: zi = z0+2 .. z0+ZCK+1, unconditional output plane zi-2
    #pragma unroll 1
    for (int zi = z0 + 2; zi <= z0 + ZCK + 1; ++zi) {
        PLANE_BODY(zi, true);
    }

    #undef PLANE_BODY
    #undef LOADP
}

extern "C" void kernel_launch(void* const* d_in, const int* in_sizes, int n_in,
                              void* d_out, int out_size) {
    (void)in_sizes; (void)n_in; (void)out_size;
    const float* img = (const float*)d_in[0];
    float* out = (float*)d_out;
    dim3 grid(X / TX, Y / TY, NB * ZCHUNKS);
    soft_skel_kernel<<<grid, NTH>>>(img, out);
}

// round 15
// speedup vs baseline: 3.4442x; 1.0631x over previous
#include <cuda_runtime.h>

#define X 256
#define Y 256
#define Z 192
#define YX (X*Y)
#define NB 2
#define TX 64           // output tile width
#define TY 32           // output tile height
#define CW 34           // float2 cells per row = (TX+4)/2
#define CH 36           // rows = TY+4 (divisible by 3)
#define TCY 12          // thread rows: each owns 3 adjacent rows
#define NTH (CW*TCY)    // 408 threads
#define ZCHUNKS 4
#define ZCK (Z/ZCHUNKS) /* 48 */

__device__ __forceinline__ float min3(float a, float b, float c) { return fminf(a, fminf(b, c)); }
__device__ __forceinline__ float max3(float a, float b, float c) { return fmaxf(a, fmaxf(b, c)); }
__device__ __forceinline__ float2 fmin3_2(float2 a, float2 b, float2 c) {
    return make_float2(min3(a.x,b.x,c.x), min3(a.y,b.y,c.y));
}
__device__ __forceinline__ float2 fmax3_2(float2 a, float2 b, float2 c) {
    return make_float2(max3(a.x,b.x,c.x), max3(a.y,b.y,c.y));
}

// out = relu(img - dilate3x3x3(erode3x3x3(img))), stride 1, pad 1.
// erode = min-pool (pad +inf), dilate = max-pool (pad -inf via domain mask).
// Thread owns THREE adjacent y-rows of one float2 cell: middle row's y-window
// is in-register; y-exchanges store only edge rows r0/r2 and read prev.r2 /
// next.r0. 4.33 uniform LDS.64 smem ops and 0.67 barrier participations per
// output voxel. Occupancy 2 (NOT 3 - the 48-reg cap at occupancy 3 caused the
// spills that sank this geometry in an earlier round). Peeled fill/steady
// z-march; ZCHUNKS=4 -> 256 blocks = one clean 2-per-SM wave.
__global__ __launch_bounds__(NTH, 2)
void soft_skel_kernel(const float* __restrict__ img, float* __restrict__ out) {
    __shared__ float2 sA[CH * CW];
    __shared__ float2 sB[CH * CW];

    const int tid = threadIdx.x;
    const int tc  = tid % CW;            // cell index
    const int tr  = tid / CW;            // owns rows 3tr, 3tr+1, 3tr+2
    const int bx0 = blockIdx.x * TX;
    const int by0 = blockIdx.y * TY;
    const int bz  = blockIdx.z;
    const int b   = bz / ZCHUNKS;
    const int z0  = (bz % ZCHUNKS) * ZCK;

    const int gx  = bx0 + 2*tc - 2;      // x of cell (even)
    const int r0  = 3*tr;                // local rows r0, r0+1, r0+2
    const int gy0 = by0 + r0 - 2;

    const bool inx  = (gx >= 0) && (gx < X);      // cell uniformly in/out in x
    const bool iny0 = (gy0     >= 0) && (gy0     < Y);
    const bool iny1 = (gy0 + 1 >= 0) && (gy0 + 1 < Y);
    const bool iny2 = (gy0 + 2 >= 0) && (gy0 + 2 < Y);

    // output: rows 2..33, cells 1..32
    const bool outC = (tc >= 1) && (tc <= CW - 2);
    const bool oRw0 = outC && (r0     >= 2) && (r0     <= 33);
    const bool oRw1 = outC && (r0 + 1 >= 2) && (r0 + 1 <= 33);
    const bool oRw2 = outC && (r0 + 2 >= 2) && (r0 + 2 <= 33);

    // smem offsets (float2 units); clamps leave garbage only in shell rows
    const int xl = (tc == 0)       ? 0      : tc - 1;
    const int xr = (tc == CW - 1)  ? CW - 1 : tc + 1;
    const int yu = (tr == 0)       ? 0      : r0 - 1;   // prev thread's r2
    const int yd = (tr == TCY - 1) ? CH - 1 : r0 + 3;   // next thread's r0
    const int o0 = (r0    ) * CW + tc;
    const int o1 = (r0 + 1) * CW + tc;
    const int o2 = (r0 + 2) * CW + tc;
    const int oU = yu * CW + tc;
    const int oD = yd * CW + tc;
    const int oL0 = (r0    ) * CW + xl, oX0 = (r0    ) * CW + xr;
    const int oL1 = (r0 + 1) * CW + xl, oX1 = (r0 + 1) * CW + xr;
    const int oL2 = (r0 + 2) * CW + xl, oX2 = (r0 + 2) * CW + xr;

    const float  PINF = __int_as_float(0x7f800000);
    const float  NINF = __int_as_float(0xff800000);
    const float2 PI2  = make_float2(PINF, PINF);
    const float2 NI2  = make_float2(NINF, NINF);

    const long base = (long)b * Z * YX + (long)gy0 * X + gx;
    const float* pIn = img + base;       // + z*YX
    float*       pO  = out + base + (long)z0 * YX;

    // rings: p = img planes (zi-2, zi-1, zi) x 3 rows; q = erode (zi-3, zi-2)
    float2 p0[3], p1[3], p2[3];
    float2 q0[3], q1[3];
    #pragma unroll
    for (int r = 0; r < 3; ++r) { q0[r] = NI2; q1[r] = NI2; }

    #define LOADP(dst, zz) do {                                                \
        const int _z = (zz);                                                   \
        const bool _zk = (unsigned)_z < (unsigned)Z;                           \
        const long _o = (long)_z * YX;                                         \
        dst[0] = (_zk && iny0 && inx) ? *(const float2*)(pIn + _o)       : PI2; \
        dst[1] = (_zk && iny1 && inx) ? *(const float2*)(pIn + _o + X)   : PI2; \
        dst[2] = (_zk && iny2 && inx) ? *(const float2*)(pIn + _o + 2*X) : PI2; \
    } while (0)

    // one plane of pipeline work at index zi (erode zc=zi-1, output zo=zi-2)
    #define PLANE_BODY(zi_, EMIT) do {                                         \
        float2 pn[3];                                                          \
        LOADP(pn, (zi_) + 1);                                                  \
        float2 zm0 = fmin3_2(p0[0], p1[0], p2[0]);                             \
        float2 zm1 = fmin3_2(p0[1], p1[1], p2[1]);                             \
        float2 zm2 = fmin3_2(p0[2], p1[2], p2[2]);                             \
        sA[o0] = zm0;                                                          \
        sA[o2] = zm2;                                                          \
        __syncthreads();                                                       \
        float2 U = sA[oU];                                                     \
        float2 D = sA[oD];                                                     \
        float2 yb0 = fmin3_2(U,   zm0, zm1);                                   \
        float2 yb1 = fmin3_2(zm0, zm1, zm2);                                   \
        float2 yb2 = fmin3_2(zm1, zm2, D);                                     \
        sB[o0] = yb0;                                                          \
        sB[o1] = yb1;                                                          \
        sB[o2] = yb2;                                                          \
        __syncthreads();                                                       \
        const bool zin = (unsigned)((zi_) - 1) < (unsigned)Z;                  \
        float2 en0, en1, en2;                                                  \
        {                                                                      \
            float2 L0 = sB[oL0], R0 = sB[oX0];                                 \
            float2 L1 = sB[oL1], R1 = sB[oX1];                                 \
            float2 L2 = sB[oL2], R2 = sB[oX2];                                 \
            const bool m0 = zin && iny0 && inx;                                \
            const bool m1 = zin && iny1 && inx;                                \
            const bool m2 = zin && iny2 && inx;                                \
            en0.x = m0 ? min3(L0.y,  yb0.x, yb0.y) : NINF;                     \
            en0.y = m0 ? min3(yb0.x, yb0.y, R0.x)  : NINF;                     \
            en1.x = m1 ? min3(L1.y,  yb1.x, yb1.y) : NINF;                     \
            en1.y = m1 ? min3(yb1.x, yb1.y, R1.x)  : NINF;                     \
            en2.x = m2 ? min3(L2.y,  yb2.x, yb2.y) : NINF;                     \
            en2.y = m2 ? min3(yb2.x, yb2.y, R2.x)  : NINF;                     \
        }                                                                      \
        float2 dd0 = fmax3_2(q0[0], q1[0], en0);                               \
        float2 dd1 = fmax3_2(q0[1], q1[1], en1);                               \
        float2 dd2 = fmax3_2(q0[2], q1[2], en2);                               \
        q0[0] = q1[0]; q1[0] = en0;                                            \
        q0[1] = q1[1]; q1[1] = en1;                                            \
        q0[2] = q1[2]; q1[2] = en2;                                            \
        sA[o0] = dd0;                                                          \
        sA[o2] = dd2;                                                          \
        __syncthreads();                                                       \
        float2 U2 = sA[oU];                                                    \
        float2 D2 = sA[oD];                                                    \
        float2 m0 = fmax3_2(U2,  dd0, dd1);                                    \
        float2 m1 = fmax3_2(dd0, dd1, dd2);                                    \
        float2 m2 = fmax3_2(dd1, dd2, D2);                                     \
        sB[o0] = m0;                                                           \
        sB[o1] = m1;                                                           \
        sB[o2] = m2;                                                           \
        __syncthreads();                                                       \
        if (EMIT) {                                                            \
            float2 L0 = sB[oL0], R0 = sB[oX0];                                 \
            float2 L1 = sB[oL1], R1 = sB[oX1];                                 \
            float2 L2 = sB[oL2], R2 = sB[oX2];                                 \
            if (oRw0) {                                                        \
                float2 r;                                                      \
                r.x = fmaxf(p0[0].x - max3(L0.y,  m0.x, m0.y), 0.0f);          \
                r.y = fmaxf(p0[0].y - max3(m0.x, m0.y, R0.x),  0.0f);          \
                *(float2*)pO = r;                 /* p0 = img at plane zo */   \
            }                                                                  \
            if (oRw1) {                                                        \
                float2 r;                                                      \
                r.x = fmaxf(p0[1].x - max3(L1.y,  m1.x, m1.y), 0.0f);          \
                r.y = fmaxf(p0[1].y - max3(m1.x, m1.y, R1.x),  0.0f);          \
                *(float2*)(pO + X) = r;                                        \
            }                                                                  \
            if (oRw2) {                                                        \
                float2 r;                                                      \
                r.x = fmaxf(p0[2].x - max3(L2.y,  m2.x, m2.y), 0.0f);          \
                r.y = fmaxf(p0[2].y - max3(m2.x, m2.y, R2.x),  0.0f);          \
                *(float2*)(pO + 2*X) = r;                                      \
            }                                                                  \
            pO += YX;                                                          \
        }                                                                      \
        p0[0] = p1[0]; p1[0] = p2[0]; p2[0] = pn[0];                           \
        p0[1] = p1[1]; p1[1] = p2[1]; p2[1] = pn[1];                           \
        p0[2] = p1[2]; p1[2] = p2[2]; p2[2] = pn[2];                           \
    } while (0)

    // ---- direct ring preload: img planes z0-2, z0-1, z0 (no smem, no sync)
    LOADP(p0, z0 - 2);
    LOADP(p1, z0 - 1);
    LOADP(p2, z0);

    // ---- FILL: bodies at zi = z0, z0+1 compute erode z0-1, z0 (no output)
    PLANE_BODY(z0,     false);
    PLANE_BODY(z0 + 1, false);

    // ---- STEADY: zi = z0+2 .. z0+ZCK+1, unconditional output plane zi-2
    #pragma unroll 1
    for (int zi = z0 + 2; zi <= z0 + ZCK + 1; ++zi) {
        PLANE_BODY(zi, true);
    }

    #undef PLANE_BODY
    #undef LOADP
}

extern "C" void kernel_launch(void* const* d_in, const int* in_sizes, int n_in,
                              void* d_out, int out_size) {
    (void)in_sizes; (void)n_in; (void)out_size;
    const float* img = (const float*)d_in[0];
    float* out = (float*)d_out;
    dim3 grid(X / TX, Y / TY, NB * ZCHUNKS);
    soft_skel_kernel<<<grid, NTH>>>(img, out);
}

// round 16
// speedup vs baseline: 3.5845x; 1.0407x over previous
#include <cuda_runtime.h>

#define X 256
#define Y 256
#define Z 192
#define YX (X*Y)
#define NB 2
#define TX 64           // output tile width
#define TY 32           // output tile height
#define CW 34           // float2 cells per row = (TX+4)/2
#define CH 36           // rows = TY+4 (divisible by 4)
#define TCY 9           // thread rows: each owns 4 adjacent rows
#define NTH (CW*TCY)    // 306 threads
#define ZCHUNKS 4
#define ZCK (Z/ZCHUNKS) /* 48 */

__device__ __forceinline__ float min3(float a, float b, float c) { return fminf(a, fminf(b, c)); }
__device__ __forceinline__ float max3(float a, float b, float c) { return fmaxf(a, fmaxf(b, c)); }
__device__ __forceinline__ float2 fmin3_2(float2 a, float2 b, float2 c) {
    return make_float2(min3(a.x,b.x,c.x), min3(a.y,b.y,c.y));
}
__device__ __forceinline__ float2 fmax3_2(float2 a, float2 b, float2 c) {
    return make_float2(max3(a.x,b.x,c.x), max3(a.y,b.y,c.y));
}

// out = relu(img - dilate3x3x3(erode3x3x3(img))), stride 1, pad 1.
// erode = min-pool (pad +inf), dilate = max-pool (pad -inf via domain mask).
// Thread owns FOUR adjacent y-rows of one float2 cell: interior rows' y-
// windows are in-register; y-exchanges store only edge rows r0/r3 and read
// prev.r3 / next.r0. 4.0 uniform LDS.64 smem ops and 0.5 barrier
// participations per output voxel (champion: 4.33 / 0.67). 306 threads,
// occupancy 2 -> register budget ~107/thread, fitting the ~95-reg body
// without spills. Peeled fill/steady z-march; 256 blocks = one 2/SM wave.
__global__ __launch_bounds__(NTH, 2)
void soft_skel_kernel(const float* __restrict__ img, float* __restrict__ out) {
    __shared__ float2 sA[CH * CW];
    __shared__ float2 sB[CH * CW];

    const int tid = threadIdx.x;
    const int tc  = tid % CW;            // cell index
    const int tr  = tid / CW;            // owns rows 4tr .. 4tr+3
    const int bx0 = blockIdx.x * TX;
    const int by0 = blockIdx.y * TY;
    const int bz  = blockIdx.z;
    const int b   = bz / ZCHUNKS;
    const int z0  = (bz % ZCHUNKS) * ZCK;

    const int gx  = bx0 + 2*tc - 2;      // x of cell (even)
    const int r0  = 4*tr;                // local rows r0..r0+3
    const int gy0 = by0 + r0 - 2;

    const bool inx  = (gx >= 0) && (gx < X);      // cell uniformly in/out in x
    const bool iny0 = (gy0     >= 0) && (gy0     < Y);
    const bool iny1 = (gy0 + 1 >= 0) && (gy0 + 1 < Y);
    const bool iny2 = (gy0 + 2 >= 0) && (gy0 + 2 < Y);
    const bool iny3 = (gy0 + 3 >= 0) && (gy0 + 3 < Y);

    // output: rows 2..33, cells 1..32
    const bool outC = (tc >= 1) && (tc <= CW - 2);
    const bool oRw0 = outC && (r0     >= 2) && (r0     <= 33);
    const bool oRw1 = outC && (r0 + 1 >= 2) && (r0 + 1 <= 33);
    const bool oRw2 = outC && (r0 + 2 >= 2) && (r0 + 2 <= 33);
    const bool oRw3 = outC && (r0 + 3 >= 2) && (r0 + 3 <= 33);

    // smem offsets (float2 units); clamps leave garbage only in shell rows
    const int xl = (tc == 0)       ? 0      : tc - 1;
    const int xr = (tc == CW - 1)  ? CW - 1 : tc + 1;
    const int yu = (tr == 0)       ? 0      : r0 - 1;   // prev thread's r3
    const int yd = (tr == TCY - 1) ? CH - 1 : r0 + 4;   // next thread's r0
    const int o0 = (r0    ) * CW + tc;
    const int o1 = (r0 + 1) * CW + tc;
    const int o2 = (r0 + 2) * CW + tc;
    const int o3 = (r0 + 3) * CW + tc;
    const int oU = yu * CW + tc;
    const int oD = yd * CW + tc;
    const int oL0 = (r0    ) * CW + xl, oX0 = (r0    ) * CW + xr;
    const int oL1 = (r0 + 1) * CW + xl, oX1 = (r0 + 1) * CW + xr;
    const int oL2 = (r0 + 2) * CW + xl, oX2 = (r0 + 2) * CW + xr;
    const int oL3 = (r0 + 3) * CW + xl, oX3 = (r0 + 3) * CW + xr;

    const float  PINF = __int_as_float(0x7f800000);
    const float  NINF = __int_as_float(0xff800000);
    const float2 PI2  = make_float2(PINF, PINF);
    const float2 NI2  = make_float2(NINF, NINF);

    const long base = (long)b * Z * YX + (long)gy0 * X + gx;
    const float* pIn = img + base;       // + z*YX
    float*       pO  = out + base + (long)z0 * YX;

    // rings: p = img planes (zi-2, zi-1, zi) x 4 rows; q = erode (zi-3, zi-2)
    float2 p0[4], p1[4], p2[4];
    float2 q0[4], q1[4];
    #pragma unroll
    for (int r = 0; r < 4; ++r) { q0[r] = NI2; q1[r] = NI2; }

    #define LOADP(dst, zz) do {                                                \
        const int _z = (zz);                                                   \
        const bool _zk = (unsigned)_z < (unsigned)Z;                           \
        const long _o = (long)_z * YX;                                         \
        dst[0] = (_zk && iny0 && inx) ? *(const float2*)(pIn + _o)       : PI2; \
        dst[1] = (_zk && iny1 && inx) ? *(const float2*)(pIn + _o + X)   : PI2; \
        dst[2] = (_zk && iny2 && inx) ? *(const float2*)(pIn + _o + 2*X) : PI2; \
        dst[3] = (_zk && iny3 && inx) ? *(const float2*)(pIn + _o + 3*X) : PI2; \
    } while (0)

    // one plane of pipeline work at index zi (erode zc=zi-1, output zo=zi-2)
    #define PLANE_BODY(zi_, EMIT) do {                                         \
        float2 pn[4];                                                          \
        LOADP(pn, (zi_) + 1);                                                  \
        float2 zm0 = fmin3_2(p0[0], p1[0], p2[0]);                             \
        float2 zm1 = fmin3_2(p0[1], p1[1], p2[1]);                             \
        float2 zm2 = fmin3_2(p0[2], p1[2], p2[2]);                             \
        float2 zm3 = fmin3_2(p0[3], p1[3], p2[3]);                             \
        sA[o0] = zm0;                                                          \
        sA[o3] = zm3;                                                          \
        __syncthreads();                                                       \
        float2 U = sA[oU];                                                     \
        float2 D = sA[oD];                                                     \
        float2 yb0 = fmin3_2(U,   zm0, zm1);                                   \
        float2 yb1 = fmin3_2(zm0, zm1, zm2);                                   \
        float2 yb2 = fmin3_2(zm1, zm2, zm3);                                   \
        float2 yb3 = fmin3_2(zm2, zm3, D);                                     \
        sB[o0] = yb0;                                                          \
        sB[o1] = yb1;                                                          \
        sB[o2] = yb2;                                                          \
        sB[o3] = yb3;                                                          \
        __syncthreads();                                                       \
        const bool zin = (unsigned)((zi_) - 1) < (unsigned)Z;                  \
        float2 en0, en1, en2, en3;                                             \
        {                                                                      \
            float2 L0 = sB[oL0], R0 = sB[oX0];                                 \
            float2 L1 = sB[oL1], R1 = sB[oX1];                                 \
            float2 L2 = sB[oL2], R2 = sB[oX2];                                 \
            float2 L3 = sB[oL3], R3 = sB[oX3];                                 \
            const bool m0 = zin && iny0 && inx;                                \
            const bool m1 = zin && iny1 && inx;                                \
            const bool m2 = zin && iny2 && inx;                                \
            const bool m3 = zin && iny3 && inx;                                \
            en0.x = m0 ? min3(L0.y,  yb0.x, yb0.y) : NINF;                     \
            en0.y = m0 ? min3(yb0.x, yb0.y, R0.x)  : NINF;                     \
            en1.x = m1 ? min3(L1.y,  yb1.x, yb1.y) : NINF;                     \
            en1.y = m1 ? min3(yb1.x, yb1.y, R1.x)  : NINF;                     \
            en2.x = m2 ? min3(L2.y,  yb2.x, yb2.y) : NINF;                     \
            en2.y = m2 ? min3(yb2.x, yb2.y, R2.x)  : NINF;                     \
            en3.x = m3 ? min3(L3.y,  yb3.x, yb3.y) : NINF;                     \
            en3.y = m3 ? min3(yb3.x, yb3.y, R3.x)  : NINF;                     \
        }                                                                      \
        float2 dd0 = fmax3_2(q0[0], q1[0], en0);                               \
        float2 dd1 = fmax3_2(q0[1], q1[1], en1);                               \
        float2 dd2 = fmax3_2(q0[2], q1[2], en2);                               \
        float2 dd3 = fmax3_2(q0[3], q1[3], en3);                               \
        q0[0] = q1[0]; q1[0] = en0;                                            \
        q0[1] = q1[1]; q1[1] = en1;                                            \
        q0[2] = q1[2]; q1[2] = en2;                                            \
        q0[3] = q1[3]; q1[3] = en3;                                            \
        sA[o0] = dd0;                                                          \
        sA[o3] = dd3;                                                          \
        __syncthreads();                                                       \
        float2 U2 = sA[oU];                                                    \
        float2 D2 = sA[oD];                                                    \
        float2 m0 = fmax3_2(U2,  dd0, dd1);                                    \
        float2 m1 = fmax3_2(dd0, dd1, dd2);                                    \
        float2 m2 = fmax3_2(dd1, dd2, dd3);                                    \
        float2 m3 = fmax3_2(dd2, dd3, D2);                                     \
        sB[o0] = m0;                                                           \
        sB[o1] = m1;                                                           \
        sB[o2] = m2;                                                           \
        sB[o3] = m3;                                                           \
        __syncthreads();                                                       \
        if (EMIT) {                                                            \
            float2 L0 = sB[oL0], R0 = sB[oX0];                                 \
            float2 L1 = sB[oL1], R1 = sB[oX1];                                 \
            float2 L2 = sB[oL2], R2 = sB[oX2];                                 \
            float2 L3 = sB[oL3], R3 = sB[oX3];                                 \
            if (oRw0) {                                                        \
                float2 r;                                                      \
                r.x = fmaxf(p0[0].x - max3(L0.y,  m0.x, m0.y), 0.0f);          \
                r.y = fmaxf(p0[0].y - max3(m0.x, m0.y, R0.x),  0.0f);          \
                *(float2*)pO = r;                 /* p0 = img at plane zo */   \
            }                                                                  \
            if (oRw1) {                                                        \
                float2 r;                                                      \
                r.x = fmaxf(p0[1].x - max3(L1.y,  m1.x, m1.y), 0.0f);          \
                r.y = fmaxf(p0[1].y - max3(m1.x, m1.y, R1.x),  0.0f);          \
                *(float2*)(pO + X) = r;                                        \
            }                                                                  \
            if (oRw2) {                                                        \
                float2 r;                                                      \
                r.x = fmaxf(p0[2].x - max3(L2.y,  m2.x, m2.y), 0.0f);          \
                r.y = fmaxf(p0[2].y - max3(m2.x, m2.y, R2.x),  0.0f);          \
                *(float2*)(pO + 2*X) = r;                                      \
            }                                                                  \
            if (oRw3) {                                                        \
                float2 r;                                                      \
                r.x = fmaxf(p0[3].x - max3(L3.y,  m3.x, m3.y), 0.0f);          \
                r.y = fmaxf(p0[3].y - max3(m3.x, m3.y, R3.x),  0.0f);          \
                *(float2*)(pO + 3*X) = r;                                      \
            }                                                                  \
            pO += YX;                                                          \
        }                                                                      \
        p0[0] = p1[0]; p1[0] = p2[0]; p2[0] = pn[0];                           \
        p0[1] = p1[1]; p1[1] = p2[1]; p2[1] = pn[1];                           \
        p0[2] = p1[2]; p1[2] = p2[2]; p2[2] = pn[2];                           \
        p0[3] = p1[3]; p1[3] = p2[3]; p2[3] = pn[3];                           \
    } while (0)

    // ---- direct ring preload: img planes z0-2, z0-1, z0 (no smem, no sync)
    LOADP(p0, z0 - 2);
    LOADP(p1, z0 - 1);
    LOADP(p2, z0);

    // ---- FILL: bodies at zi = z0, z0+1 compute erode z0-1, z0 (no output)
    PLANE_BODY(z0,     false);
    PLANE_BODY(z0 + 1, false);

    // ---- STEADY: zi = z0+2 .. z0+ZCK+1, unconditional output plane zi-2
    #pragma unroll 1
    for (int zi = z0 + 2; zi <= z0 + ZCK + 1; ++zi) {
        PLANE_BODY(zi, true);
    }

    #undef PLANE_BODY
    #undef LOADP
}

extern "C" void kernel_launch(void* const* d_in, const int* in_sizes, int n_in,
                              void* d_out, int out_size) {
    (void)in_sizes; (void)n_in; (void)out_size;
    const float* img = (const float*)d_in[0];
    float* out = (float*)d_out;
    dim3 grid(X / TX, Y / TY, NB * ZCHUNKS);
    soft_skel_kernel<<<grid, NTH>>>(img, out);
}